// round 7
// baseline (speedup 1.0000x reference)
#include <cuda_runtime.h>
#include <math.h>

#define BB 4
#define SS 4096
#define HH 8
#define DD 64
#define HD (HH*DD)
#define SCALE 0.125f
#define NBH (BB*HH)          // 32 (b,h) pairs
#define CH 32                // leaves per chunk
#define CPB (SS/CH)          // 128 chunks per bh
#define HI_NODES 254         // levels 5..11 per bh

typedef unsigned long long u64;

// Global storage for tree levels 5..11 only (~2MB each, L2-resident).
__device__ float g_hiK[(size_t)NBH * HI_NODES * DD];
__device__ float g_hiV[(size_t)NBH * HI_NODES * DD];

__device__ __forceinline__ int hioff(int j) { return 256 - (256 >> j); }

// ---------- packed f32x2 helpers (sm_10x) ----------
__device__ __forceinline__ u64 fma2(u64 a, u64 b, u64 c) {
    u64 r; asm("fma.rn.f32x2 %0, %1, %2, %3;" : "=l"(r) : "l"(a), "l"(b), "l"(c));
    return r;
}
__device__ __forceinline__ u64 add2(u64 a, u64 b) {
    u64 r; asm("add.rn.f32x2 %0, %1, %2;" : "=l"(r) : "l"(a), "l"(b));
    return r;
}
__device__ __forceinline__ u64 mul2(u64 a, u64 b) {
    u64 r; asm("mul.rn.f32x2 %0, %1, %2;" : "=l"(r) : "l"(a), "l"(b));
    return r;
}
__device__ __forceinline__ u64 pack2(float lo, float hi) {
    u64 r; asm("mov.b64 %0, {%1, %2};" : "=l"(r) : "f"(lo), "f"(hi));
    return r;
}
__device__ __forceinline__ float hadd2(u64 a) {
    float lo, hi; asm("mov.b64 {%0, %1}, %2;" : "=f"(lo), "=f"(hi) : "l"(a));
    return lo + hi;
}

// ---------- 8-lane-group softmax pool, packed math ----------
// Lane `sub` (0..7) owns dims {8*sub-ish}: ulonglong2 [sub] and [sub+8] of the
// 64-float row. mask = 0xFF<<(8*g).
__device__ __forceinline__ void pool8(const float* __restrict__ kc0,
                                      const float* __restrict__ kc1,
                                      const float* __restrict__ vc0,
                                      const float* __restrict__ vc1,
                                      float* __restrict__ kout,
                                      float* __restrict__ vout,
                                      int sub, unsigned mask) {
    const u64 HALF2 = 0x3F0000003F000000ull;  // (0.5f, 0.5f)
    ulonglong2 a0 = ((const ulonglong2*)kc0)[sub], a1 = ((const ulonglong2*)kc0)[sub + 8];
    ulonglong2 b0 = ((const ulonglong2*)kc1)[sub], b1 = ((const ulonglong2*)kc1)[sub + 8];
    ulonglong2 p0, p1;
    p0.x = mul2(add2(a0.x, b0.x), HALF2);
    p0.y = mul2(add2(a0.y, b0.y), HALF2);
    p1.x = mul2(add2(a1.x, b1.x), HALF2);
    p1.y = mul2(add2(a1.y, b1.y), HALF2);
    u64 ds2 = mul2(p0.x, p0.x);
    ds2 = fma2(p0.y, p0.y, ds2); ds2 = fma2(p1.x, p1.x, ds2); ds2 = fma2(p1.y, p1.y, ds2);
    u64 d02 = mul2(p0.x, a0.x);
    d02 = fma2(p0.y, a0.y, d02); d02 = fma2(p1.x, a1.x, d02); d02 = fma2(p1.y, a1.y, d02);
    u64 d12 = mul2(p0.x, b0.x);
    d12 = fma2(p0.y, b0.y, d12); d12 = fma2(p1.x, b1.x, d12); d12 = fma2(p1.y, b1.y, d12);
    float ds = hadd2(ds2), d0 = hadd2(d02), d1 = hadd2(d12);
#pragma unroll
    for (int o = 4; o; o >>= 1) {
        ds += __shfl_xor_sync(mask, ds, o);
        d0 += __shfl_xor_sync(mask, d0, o);
        d1 += __shfl_xor_sync(mask, d1, o);
    }
    float ss = ds * SCALE, s0 = d0 * SCALE, s1 = d1 * SCALE;
    float m  = fmaxf(ss, fmaxf(s0, s1));
    float es = __expf(ss - m), e0 = __expf(s0 - m), e1 = __expf(s1 - m);
    float inv = 1.0f / (es + e0 + e1 + 1e-9f);
    float he = 0.5f * es * inv, f0 = e0 * inv, f1 = e1 * inv;
    u64 HE2 = pack2(he, he), F02 = pack2(f0, f0), F12 = pack2(f1, f1);
    ulonglong2 va0 = ((const ulonglong2*)vc0)[sub], va1 = ((const ulonglong2*)vc0)[sub + 8];
    ulonglong2 vb0 = ((const ulonglong2*)vc1)[sub], vb1 = ((const ulonglong2*)vc1)[sub + 8];
    ulonglong2 o0, o1;
    o0.x = fma2(F12, vb0.x, fma2(F02, va0.x, mul2(add2(va0.x, vb0.x), HE2)));
    o0.y = fma2(F12, vb0.y, fma2(F02, va0.y, mul2(add2(va0.y, vb0.y), HE2)));
    o1.x = fma2(F12, vb1.x, fma2(F02, va1.x, mul2(add2(va1.x, vb1.x), HE2)));
    o1.y = fma2(F12, vb1.y, fma2(F02, va1.y, mul2(add2(va1.y, vb1.y), HE2)));
    ((ulonglong2*)kout)[sub] = p0;  ((ulonglong2*)kout)[sub + 8] = p1;
    ((ulonglong2*)vout)[sub] = o0;  ((ulonglong2*)vout)[sub + 8] = o1;
}

// Warp-collective full-dim pool for build_high only (cold path, scalar).
__device__ __forceinline__ void poolp(const float* __restrict__ kc0,
                                      const float* __restrict__ kc1,
                                      const float* __restrict__ vc0,
                                      const float* __restrict__ vc1,
                                      float* __restrict__ kout,
                                      float* __restrict__ vout, int lane) {
    float2 a  = *(const float2*)(kc0 + 2 * lane);
    float2 b  = *(const float2*)(kc1 + 2 * lane);
    float2 va = *(const float2*)(vc0 + 2 * lane);
    float2 vb = *(const float2*)(vc1 + 2 * lane);
    float2 kp;
    kp.x = 0.5f * (a.x + b.x);
    kp.y = 0.5f * (a.y + b.y);
    float ds = kp.x * kp.x + kp.y * kp.y;
    float d0 = kp.x * a.x + kp.y * a.y;
    float d1 = kp.x * b.x + kp.y * b.y;
#pragma unroll
    for (int o = 16; o; o >>= 1) {
        ds += __shfl_xor_sync(0xffffffffu, ds, o);
        d0 += __shfl_xor_sync(0xffffffffu, d0, o);
        d1 += __shfl_xor_sync(0xffffffffu, d1, o);
    }
    float ss = ds * SCALE, s0 = d0 * SCALE, s1 = d1 * SCALE;
    float m  = fmaxf(ss, fmaxf(s0, s1));
    float es = __expf(ss - m), e0 = __expf(s0 - m), e1 = __expf(s1 - m);
    float inv = 1.0f / (es + e0 + e1 + 1e-9f);
    float hes = 0.5f * es;
    float2 vp;
    vp.x = (hes * (va.x + vb.x) + e0 * va.x + e1 * vb.x) * inv;
    vp.y = (hes * (va.y + vb.y) + e0 * va.y + e1 * vb.y) * inv;
    *(float2*)(kout + 2 * lane) = kp;
    *(float2*)(vout + 2 * lane) = vp;
}

// ---------- Pass 1: per 32-leaf chunk, emit level-5 node ----------
__global__ __launch_bounds__(128) void build5(const float* __restrict__ k,
                                              const float* __restrict__ v) {
    __shared__ float sK[30 * DD], sV[30 * DD];
    int blk = blockIdx.x;
    int cc  = blk & (CPB - 1);
    int bh  = blk >> 7;
    int b = bh >> 3, h = bh & 7;
    int tid = threadIdx.x, warp = tid >> 5, lane = tid & 31;
    int g = lane >> 3, sub = lane & 7;
    unsigned gmask = 0xFFu << (g * 8);
    int slot = warp * 4 + g;

    const float* leafK = k + ((size_t)(b * SS + cc * CH) * HH + h) * DD;
    const float* leafV = v + ((size_t)(b * SS + cc * CH) * HH + h) * DD;

    pool8(leafK + (size_t)(2 * slot) * HD, leafK + (size_t)(2 * slot + 1) * HD,
          leafV + (size_t)(2 * slot) * HD, leafV + (size_t)(2 * slot + 1) * HD,
          sK + slot * DD, sV + slot * DD, sub, gmask);
    __syncthreads();
    if (slot < 8)
        pool8(sK + (2 * slot) * DD, sK + (2 * slot + 1) * DD,
              sV + (2 * slot) * DD, sV + (2 * slot + 1) * DD,
              sK + (16 + slot) * DD, sV + (16 + slot) * DD, sub, gmask);
    __syncthreads();
    if (warp == 0) {
        pool8(sK + (16 + 2 * g) * DD, sK + (16 + 2 * g + 1) * DD,
              sV + (16 + 2 * g) * DD, sV + (16 + 2 * g + 1) * DD,
              sK + (24 + g) * DD, sV + (24 + g) * DD, sub, gmask);
        __syncwarp();
        if (g < 2)
            pool8(sK + (24 + 2 * g) * DD, sK + (24 + 2 * g + 1) * DD,
                  sV + (24 + 2 * g) * DD, sV + (24 + 2 * g + 1) * DD,
                  sK + (28 + g) * DD, sV + (28 + g) * DD, sub, gmask);
        __syncwarp();
        if (g == 0) {
            size_t o = ((size_t)bh * HI_NODES + cc) * DD;
            pool8(sK + 28 * DD, sK + 29 * DD, sV + 28 * DD, sV + 29 * DD,
                  g_hiK + o, g_hiV + o, sub, 0xFFu);
        }
    }
}

// ---------- Pass 2: per bh, levels 6..11 ----------
__global__ __launch_bounds__(512) void build_high() {
    int bh = blockIdx.x;
    int warp = threadIdx.x >> 5, lane = threadIdx.x & 31;
    size_t base = (size_t)bh * HI_NODES * DD;

    int off_prev = 0, off = 128, cnt = 64;
#pragma unroll
    for (int l = 6; l <= 11; l++) {
        for (int j = warp; j < cnt; j += 16)
            poolp(g_hiK + base + (size_t)(off_prev + 2 * j) * DD,
                  g_hiK + base + (size_t)(off_prev + 2 * j + 1) * DD,
                  g_hiV + base + (size_t)(off_prev + 2 * j) * DD,
                  g_hiV + base + (size_t)(off_prev + 2 * j + 1) * DD,
                  g_hiK + base + (size_t)(off + j) * DD,
                  g_hiV + base + (size_t)(off + j) * DD, lane);
        __syncthreads();
        off_prev = off;
        off += cnt;
        cnt >>= 1;
    }
}

// ---------- Pass 3: fused attention, predicated + packed math ----------
// Smem rows: L1 0..15, L2 16..23, L3 24..27, L4 28..29, HI 30..36 (37 rows).
#define R_L2 16
#define R_L3 24
#define R_L4 28
#define R_HI 30

__device__ __forceinline__ ulonglong2 ldp2(const ulonglong2* p, bool pr) {
    ulonglong2 r; r.x = 0ull; r.y = 0ull;
    if (pr) r = *p;
    return r;
}

__global__ __launch_bounds__(256) void attn(const float* __restrict__ q,
                                            const float* __restrict__ k,
                                            const float* __restrict__ v,
                                            float* __restrict__ out) {
    __shared__ float sK[37 * DD], sV[37 * DD];
    int blk = blockIdx.x;
    int cc  = blk & (CPB - 1);
    int bh  = blk >> 7;
    int b = bh >> 3, h = bh & 7;
    int tid = threadIdx.x, warp = tid >> 5, lane = tid & 31;
    int g = lane >> 3, sub = lane & 7;
    unsigned gmask = 0xFFu << (g * 8);
    int qid = tid >> 3;

    const float* leafK = k + ((size_t)(b * SS + cc * CH) * HH + h) * DD;
    const float* leafV = v + ((size_t)(b * SS + cc * CH) * HH + h) * DD;

    size_t qoff = ((size_t)(b * SS + cc * CH + qid) * HH + h) * DD;
    ulonglong2 q0p = ((const ulonglong2*)(q + qoff))[sub];
    ulonglong2 q1p = ((const ulonglong2*)(q + qoff))[sub + 8];

    if (warp < 4) {
        int slot = warp * 4 + g;
        pool8(leafK + (size_t)(2 * slot) * HD, leafK + (size_t)(2 * slot + 1) * HD,
              leafV + (size_t)(2 * slot) * HD, leafV + (size_t)(2 * slot + 1) * HD,
              sK + slot * DD, sV + slot * DD, sub, gmask);
    } else {
        int j = (warp - 4) * 4 + g;
        if (j < 7) {
            int n = cc >> j;
            int node = (n > 0) ? n - 1 : 0;
            const float* hk = g_hiK + ((size_t)bh * HI_NODES + hioff(j) + node) * DD;
            const float* hv = g_hiV + ((size_t)bh * HI_NODES + hioff(j) + node) * DD;
            ((ulonglong2*)(sK + (R_HI + j) * DD))[sub]     = ((const ulonglong2*)hk)[sub];
            ((ulonglong2*)(sK + (R_HI + j) * DD))[sub + 8] = ((const ulonglong2*)hk)[sub + 8];
            ((ulonglong2*)(sV + (R_HI + j) * DD))[sub]     = ((const ulonglong2*)hv)[sub];
            ((ulonglong2*)(sV + (R_HI + j) * DD))[sub + 8] = ((const ulonglong2*)hv)[sub + 8];
        }
    }
    __syncthreads();
    if (warp < 2) {
        int slot = warp * 4 + g;
        pool8(sK + (2 * slot) * DD, sK + (2 * slot + 1) * DD,
              sV + (2 * slot) * DD, sV + (2 * slot + 1) * DD,
              sK + (R_L2 + slot) * DD, sV + (R_L2 + slot) * DD, sub, gmask);
    }
    __syncthreads();
    if (warp == 0) {
        pool8(sK + (R_L2 + 2 * g) * DD, sK + (R_L2 + 2 * g + 1) * DD,
              sV + (R_L2 + 2 * g) * DD, sV + (R_L2 + 2 * g + 1) * DD,
              sK + (R_L3 + g) * DD, sV + (R_L3 + g) * DD, sub, gmask);
        __syncwarp();
        if (g < 2)
            pool8(sK + (R_L3 + 2 * g) * DD, sK + (R_L3 + 2 * g + 1) * DD,
                  sV + (R_L3 + 2 * g) * DD, sV + (R_L3 + 2 * g + 1) * DD,
                  sK + (R_L4 + g) * DD, sV + (R_L4 + g) * DD, sub, gmask);
    }
    __syncthreads();

    // ---- batched 13-key attention for query qid ----
    const float* selfK = leafK + (size_t)qid * HD;
    const float* selfV = leafV + (size_t)qid * HD;
    int sib = (qid > 0) ? qid - 1 : 0;
    const float* sibK = leafK + (size_t)sib * HD;
    const float* sibV = leafV + (size_t)sib * HD;

    int rows[11];
    bool val[13];
    val[0] = true;
    val[1] = (qid & 1);
    const int tbase[4] = {0, R_L2, R_L3, R_L4};
#pragma unroll
    for (int l = 1; l <= 4; l++) {
        int n = qid >> l;
        rows[l - 1] = tbase[l - 1] + ((n > 0) ? n - 1 : 0);
        val[1 + l]  = (n & 1);
    }
#pragma unroll
    for (int j = 0; j < 7; j++) {
        rows[4 + j] = R_HI + j;
        val[6 + j]  = ((cc >> j) & 1);
    }

    // K pass: packed dots, predicated loads
    float pd[13];
    {
        ulonglong2 x0 = ((const ulonglong2*)selfK)[sub];
        ulonglong2 x1 = ((const ulonglong2*)selfK)[sub + 8];
        u64 acc = mul2(q0p.x, x0.x);
        acc = fma2(q0p.y, x0.y, acc);
        acc = fma2(q1p.x, x1.x, acc);
        acc = fma2(q1p.y, x1.y, acc);
        pd[0] = hadd2(acc);
        ulonglong2 y0 = ldp2((const ulonglong2*)sibK + sub, val[1]);
        ulonglong2 y1 = ldp2((const ulonglong2*)sibK + sub + 8, val[1]);
        acc = mul2(q0p.x, y0.x);
        acc = fma2(q0p.y, y0.y, acc);
        acc = fma2(q1p.x, y1.x, acc);
        acc = fma2(q1p.y, y1.y, acc);
        pd[1] = hadd2(acc);
    }
#pragma unroll
    for (int i = 2; i < 13; i++) {
        const ulonglong2* kr = (const ulonglong2*)(sK + rows[i - 2] * DD);
        ulonglong2 x0 = ldp2(kr + sub, val[i]);
        ulonglong2 x1 = ldp2(kr + sub + 8, val[i]);
        u64 acc = mul2(q0p.x, x0.x);
        acc = fma2(q0p.y, x0.y, acc);
        acc = fma2(q1p.x, x1.x, acc);
        acc = fma2(q1p.y, x1.y, acc);
        pd[i] = hadd2(acc);
    }
#pragma unroll
    for (int o = 4; o; o >>= 1) {
#pragma unroll
        for (int i = 0; i < 13; i++)
            pd[i] += __shfl_xor_sync(0xffffffffu, pd[i], o);
    }
    float m = -1e30f;
#pragma unroll
    for (int i = 0; i < 13; i++) {
        pd[i] = val[i] ? pd[i] * SCALE : -1e30f;
        m = fmaxf(m, pd[i]);
    }
    float denom = 0.0f;
#pragma unroll
    for (int i = 0; i < 13; i++) {
        pd[i] = val[i] ? __expf(pd[i] - m) : 0.0f;
        denom += pd[i];
    }
    // V pass: packed weighted accumulation, predicated loads
    u64 ax = 0ull, ay = 0ull, az = 0ull, aw = 0ull;
    {
        ulonglong2 y0 = ((const ulonglong2*)selfV)[sub];
        ulonglong2 y1 = ((const ulonglong2*)selfV)[sub + 8];
        u64 w2 = pack2(pd[0], pd[0]);
        ax = mul2(w2, y0.x); ay = mul2(w2, y0.y);
        az = mul2(w2, y1.x); aw = mul2(w2, y1.y);
        ulonglong2 z0 = ldp2((const ulonglong2*)sibV + sub, val[1]);
        ulonglong2 z1 = ldp2((const ulonglong2*)sibV + sub + 8, val[1]);
        w2 = pack2(pd[1], pd[1]);
        ax = fma2(w2, z0.x, ax); ay = fma2(w2, z0.y, ay);
        az = fma2(w2, z1.x, az); aw = fma2(w2, z1.y, aw);
    }
#pragma unroll
    for (int i = 2; i < 13; i++) {
        const ulonglong2* vr = (const ulonglong2*)(sV + rows[i - 2] * DD);
        ulonglong2 y0 = ldp2(vr + sub, val[i]);
        ulonglong2 y1 = ldp2(vr + sub + 8, val[i]);
        u64 w2 = pack2(pd[i], pd[i]);
        ax = fma2(w2, y0.x, ax); ay = fma2(w2, y0.y, ay);
        az = fma2(w2, y1.x, az); aw = fma2(w2, y1.y, aw);
    }
    float inv = 1.0f / denom;
    u64 inv2 = pack2(inv, inv);
    ulonglong2 o0, o1;
    o0.x = mul2(ax, inv2); o0.y = mul2(ay, inv2);
    o1.x = mul2(az, inv2); o1.y = mul2(aw, inv2);
    ((ulonglong2*)(out + qoff))[sub]     = o0;
    ((ulonglong2*)(out + qoff))[sub + 8] = o1;
}

extern "C" void kernel_launch(void* const* d_in, const int* in_sizes, int n_in,
                              void* d_out, int out_size) {
    const float* q = (const float*)d_in[0];
    const float* k = (const float*)d_in[1];
    const float* v = (const float*)d_in[2];
    float* out = (float*)d_out;

    build5<<<NBH * CPB, 128>>>(k, v);
    build_high<<<NBH, 512>>>();
    attn<<<NBH * CPB, 256>>>(q, k, v, out);
}

// round 9
// speedup vs baseline: 1.0121x; 1.0121x over previous
#include <cuda_runtime.h>
#include <math.h>

#define BB 4
#define SS 4096
#define HH 8
#define DD 64
#define HD (HH*DD)
#define SCALE 0.125f
#define NBH (BB*HH)          // 32 (b,h) pairs
#define CH 32                // leaves per chunk
#define CPB (SS/CH)          // 128 chunks per bh
#define HI_NODES 254         // levels 5..11 per bh

// Global storage for tree levels 5..11 only (~2MB each, L2-resident).
__device__ float g_hiK[(size_t)NBH * HI_NODES * DD];
__device__ float g_hiV[(size_t)NBH * HI_NODES * DD];

__device__ __forceinline__ int hioff(int j) { return 256 - (256 >> j); }

// ---------- 8-lane-group softmax pool ----------
__device__ __forceinline__ void pool8(const float* __restrict__ kc0,
                                      const float* __restrict__ kc1,
                                      const float* __restrict__ vc0,
                                      const float* __restrict__ vc1,
                                      float* __restrict__ kout,
                                      float* __restrict__ vout,
                                      int sub, unsigned mask) {
    float4 a0 = ((const float4*)kc0)[sub], a1 = ((const float4*)kc0)[sub + 8];
    float4 b0 = ((const float4*)kc1)[sub], b1 = ((const float4*)kc1)[sub + 8];
    float4 p0, p1;
    p0.x = 0.5f * (a0.x + b0.x); p0.y = 0.5f * (a0.y + b0.y);
    p0.z = 0.5f * (a0.z + b0.z); p0.w = 0.5f * (a0.w + b0.w);
    p1.x = 0.5f * (a1.x + b1.x); p1.y = 0.5f * (a1.y + b1.y);
    p1.z = 0.5f * (a1.z + b1.z); p1.w = 0.5f * (a1.w + b1.w);
    float ds = p0.x*p0.x + p0.y*p0.y + p0.z*p0.z + p0.w*p0.w
             + p1.x*p1.x + p1.y*p1.y + p1.z*p1.z + p1.w*p1.w;
    float d0 = p0.x*a0.x + p0.y*a0.y + p0.z*a0.z + p0.w*a0.w
             + p1.x*a1.x + p1.y*a1.y + p1.z*a1.z + p1.w*a1.w;
    float d1 = p0.x*b0.x + p0.y*b0.y + p0.z*b0.z + p0.w*b0.w
             + p1.x*b1.x + p1.y*b1.y + p1.z*b1.z + p1.w*b1.w;
#pragma unroll
    for (int o = 4; o; o >>= 1) {
        ds += __shfl_xor_sync(mask, ds, o);
        d0 += __shfl_xor_sync(mask, d0, o);
        d1 += __shfl_xor_sync(mask, d1, o);
    }
    float ss = ds * SCALE, s0 = d0 * SCALE, s1 = d1 * SCALE;
    float m  = fmaxf(ss, fmaxf(s0, s1));
    float es = __expf(ss - m), e0 = __expf(s0 - m), e1 = __expf(s1 - m);
    float inv = 1.0f / (es + e0 + e1 + 1e-9f);
    float hes = 0.5f * es;
    float4 va0 = ((const float4*)vc0)[sub], va1 = ((const float4*)vc0)[sub + 8];
    float4 vb0 = ((const float4*)vc1)[sub], vb1 = ((const float4*)vc1)[sub + 8];
    float4 o0, o1;
    o0.x = (hes*(va0.x+vb0.x) + e0*va0.x + e1*vb0.x) * inv;
    o0.y = (hes*(va0.y+vb0.y) + e0*va0.y + e1*vb0.y) * inv;
    o0.z = (hes*(va0.z+vb0.z) + e0*va0.z + e1*vb0.z) * inv;
    o0.w = (hes*(va0.w+vb0.w) + e0*va0.w + e1*vb0.w) * inv;
    o1.x = (hes*(va1.x+vb1.x) + e0*va1.x + e1*vb1.x) * inv;
    o1.y = (hes*(va1.y+vb1.y) + e0*va1.y + e1*vb1.y) * inv;
    o1.z = (hes*(va1.z+vb1.z) + e0*va1.z + e1*vb1.z) * inv;
    o1.w = (hes*(va1.w+vb1.w) + e0*va1.w + e1*vb1.w) * inv;
    ((float4*)kout)[sub] = p0;  ((float4*)kout)[sub + 8] = p1;
    ((float4*)vout)[sub] = o0;  ((float4*)vout)[sub + 8] = o1;
}

// Warp-collective full-dim pool for build_high only.
__device__ __forceinline__ void poolp(const float* __restrict__ kc0,
                                      const float* __restrict__ kc1,
                                      const float* __restrict__ vc0,
                                      const float* __restrict__ vc1,
                                      float* __restrict__ kout,
                                      float* __restrict__ vout, int lane) {
    float2 a  = *(const float2*)(kc0 + 2 * lane);
    float2 b  = *(const float2*)(kc1 + 2 * lane);
    float2 va = *(const float2*)(vc0 + 2 * lane);
    float2 vb = *(const float2*)(vc1 + 2 * lane);
    float2 kp;
    kp.x = 0.5f * (a.x + b.x);
    kp.y = 0.5f * (a.y + b.y);
    float ds = kp.x * kp.x + kp.y * kp.y;
    float d0 = kp.x * a.x + kp.y * a.y;
    float d1 = kp.x * b.x + kp.y * b.y;
#pragma unroll
    for (int o = 16; o; o >>= 1) {
        ds += __shfl_xor_sync(0xffffffffu, ds, o);
        d0 += __shfl_xor_sync(0xffffffffu, d0, o);
        d1 += __shfl_xor_sync(0xffffffffu, d1, o);
    }
    float ss = ds * SCALE, s0 = d0 * SCALE, s1 = d1 * SCALE;
    float m  = fmaxf(ss, fmaxf(s0, s1));
    float es = __expf(ss - m), e0 = __expf(s0 - m), e1 = __expf(s1 - m);
    float inv = 1.0f / (es + e0 + e1 + 1e-9f);
    float hes = 0.5f * es;
    float2 vp;
    vp.x = (hes * (va.x + vb.x) + e0 * va.x + e1 * vb.x) * inv;
    vp.y = (hes * (va.y + vb.y) + e0 * va.y + e1 * vb.y) * inv;
    *(float2*)(kout + 2 * lane) = kp;
    *(float2*)(vout + 2 * lane) = vp;
}

// ---------- Pass 1: per 32-leaf chunk, emit level-5 node ----------
__global__ __launch_bounds__(128, 12) void build5(const float* __restrict__ k,
                                                  const float* __restrict__ v) {
    __shared__ float sK[30 * DD], sV[30 * DD];
    int blk = blockIdx.x;
    int cc  = blk & (CPB - 1);
    int bh  = blk >> 7;
    int b = bh >> 3, h = bh & 7;
    int tid = threadIdx.x, warp = tid >> 5, lane = tid & 31;
    int g = lane >> 3, sub = lane & 7;
    unsigned gmask = 0xFFu << (g * 8);
    int slot = warp * 4 + g;

    const float* leafK = k + ((size_t)(b * SS + cc * CH) * HH + h) * DD;
    const float* leafV = v + ((size_t)(b * SS + cc * CH) * HH + h) * DD;

    pool8(leafK + (size_t)(2 * slot) * HD, leafK + (size_t)(2 * slot + 1) * HD,
          leafV + (size_t)(2 * slot) * HD, leafV + (size_t)(2 * slot + 1) * HD,
          sK + slot * DD, sV + slot * DD, sub, gmask);
    __syncthreads();
    if (slot < 8)
        pool8(sK + (2 * slot) * DD, sK + (2 * slot + 1) * DD,
              sV + (2 * slot) * DD, sV + (2 * slot + 1) * DD,
              sK + (16 + slot) * DD, sV + (16 + slot) * DD, sub, gmask);
    __syncthreads();
    if (warp == 0) {
        pool8(sK + (16 + 2 * g) * DD, sK + (16 + 2 * g + 1) * DD,
              sV + (16 + 2 * g) * DD, sV + (16 + 2 * g + 1) * DD,
              sK + (24 + g) * DD, sV + (24 + g) * DD, sub, gmask);
        __syncwarp();
        if (g < 2)
            pool8(sK + (24 + 2 * g) * DD, sK + (24 + 2 * g + 1) * DD,
                  sV + (24 + 2 * g) * DD, sV + (24 + 2 * g + 1) * DD,
                  sK + (28 + g) * DD, sV + (28 + g) * DD, sub, gmask);
        __syncwarp();
        if (g == 0) {
            size_t o = ((size_t)bh * HI_NODES + cc) * DD;
            pool8(sK + 28 * DD, sK + 29 * DD, sV + 28 * DD, sV + 29 * DD,
                  g_hiK + o, g_hiV + o, sub, 0xFFu);
        }
    }
}

// ---------- Pass 2: per bh, levels 6..11 ----------
__global__ __launch_bounds__(512) void build_high() {
    int bh = blockIdx.x;
    int warp = threadIdx.x >> 5, lane = threadIdx.x & 31;
    size_t base = (size_t)bh * HI_NODES * DD;

    int off_prev = 0, off = 128, cnt = 64;
#pragma unroll
    for (int l = 6; l <= 11; l++) {
        for (int j = warp; j < cnt; j += 16)
            poolp(g_hiK + base + (size_t)(off_prev + 2 * j) * DD,
                  g_hiK + base + (size_t)(off_prev + 2 * j + 1) * DD,
                  g_hiV + base + (size_t)(off_prev + 2 * j) * DD,
                  g_hiV + base + (size_t)(off_prev + 2 * j + 1) * DD,
                  g_hiK + base + (size_t)(off + j) * DD,
                  g_hiV + base + (size_t)(off + j) * DD, lane);
        __syncthreads();
        off_prev = off;
        off += cnt;
        cnt >>= 1;
    }
}

// ---------- Pass 3: fused attention ----------
// Smem rows: L1 0..15, L2 16..23, L3 24..27, L4 28..29, HI 30..36 (37 rows).
// Dead rows (not read by attention nor needed as build parents):
//   L1 {15}, L2 {7}, L3 {3}, L4 {1}.
#define R_L2 16
#define R_L3 24
#define R_L4 28
#define R_HI 30

__device__ __forceinline__ float4 lds4_pred(const float4* p, bool pr) {
    float4 r = {0.f, 0.f, 0.f, 0.f};
    if (pr) r = *p;
    return r;
}

__global__ __launch_bounds__(256, 5) void attn(const float* __restrict__ q,
                                               const float* __restrict__ k,
                                               const float* __restrict__ v,
                                               float* __restrict__ out) {
    __shared__ float sK[37 * DD], sV[37 * DD];
    int blk = blockIdx.x;
    int cc  = blk & (CPB - 1);
    int bh  = blk >> 7;
    int b = bh >> 3, h = bh & 7;
    int tid = threadIdx.x, warp = tid >> 5, lane = tid & 31;
    int g = lane >> 3, sub = lane & 7;
    unsigned gmask = 0xFFu << (g * 8);
    int qid = tid >> 3;

    const float* leafK = k + ((size_t)(b * SS + cc * CH) * HH + h) * DD;
    const float* leafV = v + ((size_t)(b * SS + cc * CH) * HH + h) * DD;

    size_t qoff = ((size_t)(b * SS + cc * CH + qid) * HH + h) * DD;
    float4 q0 = ((const float4*)(q + qoff))[sub];
    float4 q1 = ((const float4*)(q + qoff))[sub + 8];

    if (warp < 4) {
        int slot = warp * 4 + g;
        if (slot != 15)                 // dead L1 row
            pool8(leafK + (size_t)(2 * slot) * HD, leafK + (size_t)(2 * slot + 1) * HD,
                  leafV + (size_t)(2 * slot) * HD, leafV + (size_t)(2 * slot + 1) * HD,
                  sK + slot * DD, sV + slot * DD, sub, gmask);
    } else {
        int j = (warp - 4) * 4 + g;
        if (j < 7) {
            int n = cc >> j;
            int node = (n > 0) ? n - 1 : 0;
            const float* hk = g_hiK + ((size_t)bh * HI_NODES + hioff(j) + node) * DD;
            const float* hv = g_hiV + ((size_t)bh * HI_NODES + hioff(j) + node) * DD;
            ((float4*)(sK + (R_HI + j) * DD))[sub]     = ((const float4*)hk)[sub];
            ((float4*)(sK + (R_HI + j) * DD))[sub + 8] = ((const float4*)hk)[sub + 8];
            ((float4*)(sV + (R_HI + j) * DD))[sub]     = ((const float4*)hv)[sub];
            ((float4*)(sV + (R_HI + j) * DD))[sub + 8] = ((const float4*)hv)[sub + 8];
        }
    }
    __syncthreads();
    if (warp < 2) {
        int slot = warp * 4 + g;
        if (slot != 7)                  // dead L2 row
            pool8(sK + (2 * slot) * DD, sK + (2 * slot + 1) * DD,
                  sV + (2 * slot) * DD, sV + (2 * slot + 1) * DD,
                  sK + (R_L2 + slot) * DD, sV + (R_L2 + slot) * DD, sub, gmask);
    }
    __syncthreads();
    if (warp == 0) {
        if (g < 3)                       // L3 row 3 dead
            pool8(sK + (R_L2 + 2 * g) * DD, sK + (R_L2 + 2 * g + 1) * DD,
                  sV + (R_L2 + 2 * g) * DD, sV + (R_L2 + 2 * g + 1) * DD,
                  sK + (R_L3 + g) * DD, sV + (R_L3 + g) * DD, sub, gmask);
        __syncwarp();
        if (g == 0)                      // L4 row 1 dead
            pool8(sK + R_L3 * DD, sK + (R_L3 + 1) * DD,
                  sV + R_L3 * DD, sV + (R_L3 + 1) * DD,
                  sK + R_L4 * DD, sV + R_L4 * DD, sub, gmask);
    }
    __syncthreads();

    // ---- batched 13-key attention for query qid (predicated slots) ----
    const float* selfK = leafK + (size_t)qid * HD;
    const float* selfV = leafV + (size_t)qid * HD;
    int sib = (qid > 0) ? qid - 1 : 0;
    const float* sibK = leafK + (size_t)sib * HD;
    const float* sibV = leafV + (size_t)sib * HD;

    int rows[11];
    bool val[13];
    val[0] = true;
    val[1] = (qid & 1);
    const int tbase[4] = {0, R_L2, R_L3, R_L4};
#pragma unroll
    for (int l = 1; l <= 4; l++) {
        int n = qid >> l;
        rows[l - 1] = tbase[l - 1] + ((n > 0) ? n - 1 : 0);
        val[1 + l]  = (n & 1);
    }
#pragma unroll
    for (int j = 0; j < 7; j++) {
        rows[4 + j] = R_HI + j;
        val[6 + j]  = ((cc >> j) & 1);
    }

    // K pass
    float pd[13];
    {
        float4 x0 = ((const float4*)selfK)[sub], x1 = ((const float4*)selfK)[sub + 8];
        pd[0] = q0.x*x0.x + q0.y*x0.y + q0.z*x0.z + q0.w*x0.w
              + q1.x*x1.x + q1.y*x1.y + q1.z*x1.z + q1.w*x1.w;
        float4 y0 = lds4_pred((const float4*)sibK + sub, val[1]);
        float4 y1 = lds4_pred((const float4*)sibK + sub + 8, val[1]);
        pd[1] = q0.x*y0.x + q0.y*y0.y + q0.z*y0.z + q0.w*y0.w
              + q1.x*y1.x + q1.y*y1.y + q1.z*y1.z + q1.w*y1.w;
    }
#pragma unroll
    for (int i = 2; i < 13; i++) {
        const float4* kr = (const float4*)(sK + rows[i - 2] * DD);
        float4 x0 = lds4_pred(kr + sub, val[i]);
        float4 x1 = lds4_pred(kr + sub + 8, val[i]);
        pd[i] = q0.x*x0.x + q0.y*x0.y + q0.z*x0.z + q0.w*x0.w
              + q1.x*x1.x + q1.y*x1.y + q1.z*x1.z + q1.w*x1.w;
    }
#pragma unroll
    for (int o = 4; o; o >>= 1) {
#pragma unroll
        for (int i = 0; i < 13; i++)
            pd[i] += __shfl_xor_sync(0xffffffffu, pd[i], o);
    }
    float m = -1e30f;
#pragma unroll
    for (int i = 0; i < 13; i++) {
        pd[i] = val[i] ? pd[i] * SCALE : -1e30f;
        m = fmaxf(m, pd[i]);
    }
    float denom = 0.0f;
#pragma unroll
    for (int i = 0; i < 13; i++) {
        pd[i] = val[i] ? __expf(pd[i] - m) : 0.0f;
        denom += pd[i];
    }
    // V pass
    float4 a0, a1;
    {
        float4 y0 = ((const float4*)selfV)[sub], y1 = ((const float4*)selfV)[sub + 8];
        float w = pd[0];
        a0.x = w * y0.x; a0.y = w * y0.y; a0.z = w * y0.z; a0.w = w * y0.w;
        a1.x = w * y1.x; a1.y = w * y1.y; a1.z = w * y1.z; a1.w = w * y1.w;
        float4 z0 = lds4_pred((const float4*)sibV + sub, val[1]);
        float4 z1 = lds4_pred((const float4*)sibV + sub + 8, val[1]);
        w = pd[1];
        a0.x += w * z0.x; a0.y += w * z0.y; a0.z += w * z0.z; a0.w += w * z0.w;
        a1.x += w * z1.x; a1.y += w * z1.y; a1.z += w * z1.z; a1.w += w * z1.w;
    }
#pragma unroll
    for (int i = 2; i < 13; i++) {
        const float4* vr = (const float4*)(sV + rows[i - 2] * DD);
        float4 y0 = lds4_pred(vr + sub, val[i]);
        float4 y1 = lds4_pred(vr + sub + 8, val[i]);
        float w = pd[i];
        a0.x += w * y0.x; a0.y += w * y0.y; a0.z += w * y0.z; a0.w += w * y0.w;
        a1.x += w * y1.x; a1.y += w * y1.y; a1.z += w * y1.z; a1.w += w * y1.w;
    }
    float inv = 1.0f / denom;
    a0.x *= inv; a0.y *= inv; a0.z *= inv; a0.w *= inv;
    a1.x *= inv; a1.y *= inv; a1.z *= inv; a1.w *= inv;
    ((float4*)(out + qoff))[sub]     = a0;
    ((float4*)(out + qoff))[sub + 8] = a1;
}

extern "C" void kernel_launch(void* const* d_in, const int* in_sizes, int n_in,
                              void* d_out, int out_size) {
    const float* q = (const float*)d_in[0];
    const float* k = (const float*)d_in[1];
    const float* v = (const float*)d_in[2];
    float* out = (float*)d_out;

    build5<<<NBH * CPB, 128>>>(k, v);
    build_high<<<NBH, 512>>>();
    attn<<<NBH * CPB, 256>>>(q, k, v, out);
}

// round 10
// speedup vs baseline: 1.0490x; 1.0365x over previous
#include <cuda_runtime.h>
#include <math.h>

#define BB 4
#define SS 4096
#define HH 8
#define DD 64
#define HD (HH*DD)
#define SCALE 0.125f
#define NBH (BB*HH)          // 32 (b,h) pairs
#define CH 32                // leaves per chunk
#define CPB (SS/CH)          // 128 chunks per bh
#define HI_NODES 254         // levels 5..11 per bh

// Global storage for tree levels 5..11 only (~2MB each, L2-resident).
__device__ float g_hiK[(size_t)NBH * HI_NODES * DD];
__device__ float g_hiV[(size_t)NBH * HI_NODES * DD];

__device__ __forceinline__ int hioff(int j) { return 256 - (256 >> j); }

// ---------- 8-lane-group softmax pool ----------
__device__ __forceinline__ void pool8(const float* __restrict__ kc0,
                                      const float* __restrict__ kc1,
                                      const float* __restrict__ vc0,
                                      const float* __restrict__ vc1,
                                      float* __restrict__ kout,
                                      float* __restrict__ vout,
                                      int sub, unsigned mask) {
    float4 a0 = ((const float4*)kc0)[sub], a1 = ((const float4*)kc0)[sub + 8];
    float4 b0 = ((const float4*)kc1)[sub], b1 = ((const float4*)kc1)[sub + 8];
    float4 p0, p1;
    p0.x = 0.5f * (a0.x + b0.x); p0.y = 0.5f * (a0.y + b0.y);
    p0.z = 0.5f * (a0.z + b0.z); p0.w = 0.5f * (a0.w + b0.w);
    p1.x = 0.5f * (a1.x + b1.x); p1.y = 0.5f * (a1.y + b1.y);
    p1.z = 0.5f * (a1.z + b1.z); p1.w = 0.5f * (a1.w + b1.w);
    float ds = p0.x*p0.x + p0.y*p0.y + p0.z*p0.z + p0.w*p0.w
             + p1.x*p1.x + p1.y*p1.y + p1.z*p1.z + p1.w*p1.w;
    float d0 = p0.x*a0.x + p0.y*a0.y + p0.z*a0.z + p0.w*a0.w
             + p1.x*a1.x + p1.y*a1.y + p1.z*a1.z + p1.w*a1.w;
    float d1 = p0.x*b0.x + p0.y*b0.y + p0.z*b0.z + p0.w*b0.w
             + p1.x*b1.x + p1.y*b1.y + p1.z*b1.z + p1.w*b1.w;
#pragma unroll
    for (int o = 4; o; o >>= 1) {
        ds += __shfl_xor_sync(mask, ds, o);
        d0 += __shfl_xor_sync(mask, d0, o);
        d1 += __shfl_xor_sync(mask, d1, o);
    }
    float ss = ds * SCALE, s0 = d0 * SCALE, s1 = d1 * SCALE;
    float m  = fmaxf(ss, fmaxf(s0, s1));
    float es = __expf(ss - m), e0 = __expf(s0 - m), e1 = __expf(s1 - m);
    float inv = 1.0f / (es + e0 + e1 + 1e-9f);
    float hes = 0.5f * es;
    float4 va0 = ((const float4*)vc0)[sub], va1 = ((const float4*)vc0)[sub + 8];
    float4 vb0 = ((const float4*)vc1)[sub], vb1 = ((const float4*)vc1)[sub + 8];
    float4 o0, o1;
    o0.x = (hes*(va0.x+vb0.x) + e0*va0.x + e1*vb0.x) * inv;
    o0.y = (hes*(va0.y+vb0.y) + e0*va0.y + e1*vb0.y) * inv;
    o0.z = (hes*(va0.z+vb0.z) + e0*va0.z + e1*vb0.z) * inv;
    o0.w = (hes*(va0.w+vb0.w) + e0*va0.w + e1*vb0.w) * inv;
    o1.x = (hes*(va1.x+vb1.x) + e0*va1.x + e1*vb1.x) * inv;
    o1.y = (hes*(va1.y+vb1.y) + e0*va1.y + e1*vb1.y) * inv;
    o1.z = (hes*(va1.z+vb1.z) + e0*va1.z + e1*vb1.z) * inv;
    o1.w = (hes*(va1.w+vb1.w) + e0*va1.w + e1*vb1.w) * inv;
    ((float4*)kout)[sub] = p0;  ((float4*)kout)[sub + 8] = p1;
    ((float4*)vout)[sub] = o0;  ((float4*)vout)[sub + 8] = o1;
}

// Warp-collective full-dim pool for build_high only.
__device__ __forceinline__ void poolp(const float* __restrict__ kc0,
                                      const float* __restrict__ kc1,
                                      const float* __restrict__ vc0,
                                      const float* __restrict__ vc1,
                                      float* __restrict__ kout,
                                      float* __restrict__ vout, int lane) {
    float2 a  = *(const float2*)(kc0 + 2 * lane);
    float2 b  = *(const float2*)(kc1 + 2 * lane);
    float2 va = *(const float2*)(vc0 + 2 * lane);
    float2 vb = *(const float2*)(vc1 + 2 * lane);
    float2 kp;
    kp.x = 0.5f * (a.x + b.x);
    kp.y = 0.5f * (a.y + b.y);
    float ds = kp.x * kp.x + kp.y * kp.y;
    float d0 = kp.x * a.x + kp.y * a.y;
    float d1 = kp.x * b.x + kp.y * b.y;
#pragma unroll
    for (int o = 16; o; o >>= 1) {
        ds += __shfl_xor_sync(0xffffffffu, ds, o);
        d0 += __shfl_xor_sync(0xffffffffu, d0, o);
        d1 += __shfl_xor_sync(0xffffffffu, d1, o);
    }
    float ss = ds * SCALE, s0 = d0 * SCALE, s1 = d1 * SCALE;
    float m  = fmaxf(ss, fmaxf(s0, s1));
    float es = __expf(ss - m), e0 = __expf(s0 - m), e1 = __expf(s1 - m);
    float inv = 1.0f / (es + e0 + e1 + 1e-9f);
    float hes = 0.5f * es;
    float2 vp;
    vp.x = (hes * (va.x + vb.x) + e0 * va.x + e1 * vb.x) * inv;
    vp.y = (hes * (va.y + vb.y) + e0 * va.y + e1 * vb.y) * inv;
    *(float2*)(kout + 2 * lane) = kp;
    *(float2*)(vout + 2 * lane) = vp;
}

// ---------- Pass 1: per 32-leaf chunk, emit level-5 node ----------
__global__ __launch_bounds__(128, 12) void build5(const float* __restrict__ k,
                                                  const float* __restrict__ v) {
    __shared__ float sK[30 * DD], sV[30 * DD];
    int blk = blockIdx.x;
    int cc  = blk & (CPB - 1);
    int bh  = blk >> 7;
    int b = bh >> 3, h = bh & 7;
    int tid = threadIdx.x, warp = tid >> 5, lane = tid & 31;
    int g = lane >> 3, sub = lane & 7;
    unsigned gmask = 0xFFu << (g * 8);
    int slot = warp * 4 + g;

    const float* leafK = k + ((size_t)(b * SS + cc * CH) * HH + h) * DD;
    const float* leafV = v + ((size_t)(b * SS + cc * CH) * HH + h) * DD;

    pool8(leafK + (size_t)(2 * slot) * HD, leafK + (size_t)(2 * slot + 1) * HD,
          leafV + (size_t)(2 * slot) * HD, leafV + (size_t)(2 * slot + 1) * HD,
          sK + slot * DD, sV + slot * DD, sub, gmask);
    __syncthreads();
    if (slot < 8)
        pool8(sK + (2 * slot) * DD, sK + (2 * slot + 1) * DD,
              sV + (2 * slot) * DD, sV + (2 * slot + 1) * DD,
              sK + (16 + slot) * DD, sV + (16 + slot) * DD, sub, gmask);
    __syncthreads();
    if (warp == 0) {
        pool8(sK + (16 + 2 * g) * DD, sK + (16 + 2 * g + 1) * DD,
              sV + (16 + 2 * g) * DD, sV + (16 + 2 * g + 1) * DD,
              sK + (24 + g) * DD, sV + (24 + g) * DD, sub, gmask);
        __syncwarp();
        if (g < 2)
            pool8(sK + (24 + 2 * g) * DD, sK + (24 + 2 * g + 1) * DD,
                  sV + (24 + 2 * g) * DD, sV + (24 + 2 * g + 1) * DD,
                  sK + (28 + g) * DD, sV + (28 + g) * DD, sub, gmask);
        __syncwarp();
        if (g == 0) {
            size_t o = ((size_t)bh * HI_NODES + cc) * DD;
            pool8(sK + 28 * DD, sK + 29 * DD, sV + 28 * DD, sV + 29 * DD,
                  g_hiK + o, g_hiV + o, sub, 0xFFu);
        }
    }
}

// ---------- Pass 2: per bh, levels 6..11 ----------
__global__ __launch_bounds__(512) void build_high() {
    int bh = blockIdx.x;
    int warp = threadIdx.x >> 5, lane = threadIdx.x & 31;
    size_t base = (size_t)bh * HI_NODES * DD;

    int off_prev = 0, off = 128, cnt = 64;
#pragma unroll
    for (int l = 6; l <= 11; l++) {
        for (int j = warp; j < cnt; j += 16)
            poolp(g_hiK + base + (size_t)(off_prev + 2 * j) * DD,
                  g_hiK + base + (size_t)(off_prev + 2 * j + 1) * DD,
                  g_hiV + base + (size_t)(off_prev + 2 * j) * DD,
                  g_hiV + base + (size_t)(off_prev + 2 * j + 1) * DD,
                  g_hiK + base + (size_t)(off + j) * DD,
                  g_hiV + base + (size_t)(off + j) * DD, lane);
        __syncthreads();
        off_prev = off;
        off += cnt;
        cnt >>= 1;
    }
}

// ---------- Pass 3: fused attention ----------
// Smem rows: L1 0..15, L2 16..23, L3 24..27, L4 28..29, HI 30..36 (37 rows).
// Dead rows: L1 {15}, L2 {7}, L3 {3}, L4 {1}.
// Slot validity: slot1,2 vary within warp (predicated); slots 3..12 are
// warp-uniform (slot3 = w&1, slot4 = (w>>1)&1, slot5 = w>>2, slots 6..12 = cc
// bits, block-uniform) -> real branches skip the whole slot pipeline.
#define R_L2 16
#define R_L3 24
#define R_L4 28
#define R_HI 30

__device__ __forceinline__ float4 lds4_pred(const float4* p, bool pr) {
    float4 r = {0.f, 0.f, 0.f, 0.f};
    if (pr) r = *p;
    return r;
}

__global__ __launch_bounds__(256, 5) void attn(const float* __restrict__ q,
                                               const float* __restrict__ k,
                                               const float* __restrict__ v,
                                               float* __restrict__ out) {
    __shared__ float sK[37 * DD], sV[37 * DD];
    int blk = blockIdx.x;
    int cc  = blk & (CPB - 1);
    int bh  = blk >> 7;
    int b = bh >> 3, h = bh & 7;
    int tid = threadIdx.x, warp = tid >> 5, lane = tid & 31;
    int g = lane >> 3, sub = lane & 7;
    unsigned gmask = 0xFFu << (g * 8);
    int qid = tid >> 3;

    const float* leafK = k + ((size_t)(b * SS + cc * CH) * HH + h) * DD;
    const float* leafV = v + ((size_t)(b * SS + cc * CH) * HH + h) * DD;

    size_t qoff = ((size_t)(b * SS + cc * CH + qid) * HH + h) * DD;
    float4 q0 = ((const float4*)(q + qoff))[sub];
    float4 q1 = ((const float4*)(q + qoff))[sub + 8];

    if (warp < 4) {
        int slot = warp * 4 + g;
        if (slot != 15)                 // dead L1 row
            pool8(leafK + (size_t)(2 * slot) * HD, leafK + (size_t)(2 * slot + 1) * HD,
                  leafV + (size_t)(2 * slot) * HD, leafV + (size_t)(2 * slot + 1) * HD,
                  sK + slot * DD, sV + slot * DD, sub, gmask);
    } else {
        int j = (warp - 4) * 4 + g;
        if (j < 7) {
            int n = cc >> j;
            int node = (n > 0) ? n - 1 : 0;
            const float* hk = g_hiK + ((size_t)bh * HI_NODES + hioff(j) + node) * DD;
            const float* hv = g_hiV + ((size_t)bh * HI_NODES + hioff(j) + node) * DD;
            ((float4*)(sK + (R_HI + j) * DD))[sub]     = ((const float4*)hk)[sub];
            ((float4*)(sK + (R_HI + j) * DD))[sub + 8] = ((const float4*)hk)[sub + 8];
            ((float4*)(sV + (R_HI + j) * DD))[sub]     = ((const float4*)hv)[sub];
            ((float4*)(sV + (R_HI + j) * DD))[sub + 8] = ((const float4*)hv)[sub + 8];
        }
    }
    __syncthreads();
    // L2..L4 all on warp 0 (saves one block barrier)
    if (warp == 0) {
        // L2 live slots 0..6 (slot 7 dead), two rounds of 4 groups
        pool8(sK + (2 * g) * DD, sK + (2 * g + 1) * DD,
              sV + (2 * g) * DD, sV + (2 * g + 1) * DD,
              sK + (R_L2 + g) * DD, sV + (R_L2 + g) * DD, sub, gmask);
        if (g < 3) {
            int s2 = g + 4;
            pool8(sK + (2 * s2) * DD, sK + (2 * s2 + 1) * DD,
                  sV + (2 * s2) * DD, sV + (2 * s2 + 1) * DD,
                  sK + (R_L2 + s2) * DD, sV + (R_L2 + s2) * DD, sub, gmask);
        }
        __syncwarp();
        if (g < 3)                       // L3 row 3 dead
            pool8(sK + (R_L2 + 2 * g) * DD, sK + (R_L2 + 2 * g + 1) * DD,
                  sV + (R_L2 + 2 * g) * DD, sV + (R_L2 + 2 * g + 1) * DD,
                  sK + (R_L3 + g) * DD, sV + (R_L3 + g) * DD, sub, gmask);
        __syncwarp();
        if (g == 0)                      // L4 row 1 dead
            pool8(sK + R_L3 * DD, sK + (R_L3 + 1) * DD,
                  sV + R_L3 * DD, sV + (R_L3 + 1) * DD,
                  sK + R_L4 * DD, sV + R_L4 * DD, sub, gmask);
    }
    __syncthreads();

    // ---- batched 13-key attention for query qid ----
    const float* selfK = leafK + (size_t)qid * HD;
    const float* selfV = leafV + (size_t)qid * HD;
    int sib = (qid > 0) ? qid - 1 : 0;
    const float* sibK = leafK + (size_t)sib * HD;
    const float* sibV = leafV + (size_t)sib * HD;

    int rows[11];
    bool val[13];
    val[0] = true;
    val[1] = (qid & 1);
    const int tbase[4] = {0, R_L2, R_L3, R_L4};
#pragma unroll
    for (int l = 1; l <= 4; l++) {
        int n = qid >> l;
        rows[l - 1] = tbase[l - 1] + ((n > 0) ? n - 1 : 0);
        val[1 + l]  = (n & 1);
    }
#pragma unroll
    for (int j = 0; j < 7; j++) {
        rows[4 + j] = R_HI + j;
        val[6 + j]  = ((cc >> j) & 1);
    }

    // K pass: slots 0..2 straight/predicated, slots 3..12 branch-guarded
    float pd[13];
    {
        float4 x0 = ((const float4*)selfK)[sub], x1 = ((const float4*)selfK)[sub + 8];
        pd[0] = q0.x*x0.x + q0.y*x0.y + q0.z*x0.z + q0.w*x0.w
              + q1.x*x1.x + q1.y*x1.y + q1.z*x1.z + q1.w*x1.w;
        float4 y0 = lds4_pred((const float4*)sibK + sub, val[1]);
        float4 y1 = lds4_pred((const float4*)sibK + sub + 8, val[1]);
        pd[1] = q0.x*y0.x + q0.y*y0.y + q0.z*y0.z + q0.w*y0.w
              + q1.x*y1.x + q1.y*y1.y + q1.z*y1.z + q1.w*y1.w;
        const float4* kr = (const float4*)(sK + rows[0] * DD);
        float4 z0 = lds4_pred(kr + sub, val[2]);
        float4 z1 = lds4_pred(kr + sub + 8, val[2]);
        pd[2] = q0.x*z0.x + q0.y*z0.y + q0.z*z0.z + q0.w*z0.w
              + q1.x*z1.x + q1.y*z1.y + q1.z*z1.z + q1.w*z1.w;
    }
#pragma unroll
    for (int i = 3; i < 13; i++) {
        pd[i] = 0.0f;
        if (val[i]) {                   // warp-uniform branch
            const float4* kr = (const float4*)(sK + rows[i - 2] * DD);
            float4 x0 = kr[sub], x1 = kr[sub + 8];
            pd[i] = q0.x*x0.x + q0.y*x0.y + q0.z*x0.z + q0.w*x0.w
                  + q1.x*x1.x + q1.y*x1.y + q1.z*x1.z + q1.w*x1.w;
        }
    }
#pragma unroll
    for (int o = 4; o; o >>= 1) {
#pragma unroll
        for (int i = 0; i < 13; i++)
            pd[i] += __shfl_xor_sync(0xffffffffu, pd[i], o);
    }
    float m = -1e30f;
#pragma unroll
    for (int i = 0; i < 13; i++) {
        pd[i] = val[i] ? pd[i] * SCALE : -1e30f;
        m = fmaxf(m, pd[i]);
    }

    // Fused exp + V accumulation
    float denom;
    float4 a0, a1;
    {
        float w = __expf(pd[0] - m);
        denom = w;
        float4 y0 = ((const float4*)selfV)[sub], y1 = ((const float4*)selfV)[sub + 8];
        a0.x = w * y0.x; a0.y = w * y0.y; a0.z = w * y0.z; a0.w = w * y0.w;
        a1.x = w * y1.x; a1.y = w * y1.y; a1.z = w * y1.z; a1.w = w * y1.w;
        w = val[1] ? __expf(pd[1] - m) : 0.0f;
        denom += w;
        float4 z0 = lds4_pred((const float4*)sibV + sub, val[1]);
        float4 z1 = lds4_pred((const float4*)sibV + sub + 8, val[1]);
        a0.x += w * z0.x; a0.y += w * z0.y; a0.z += w * z0.z; a0.w += w * z0.w;
        a1.x += w * z1.x; a1.y += w * z1.y; a1.z += w * z1.z; a1.w += w * z1.w;
        w = val[2] ? __expf(pd[2] - m) : 0.0f;
        denom += w;
        const float4* vr = (const float4*)(sV + rows[0] * DD);
        float4 u0 = lds4_pred(vr + sub, val[2]);
        float4 u1 = lds4_pred(vr + sub + 8, val[2]);
        a0.x += w * u0.x; a0.y += w * u0.y; a0.z += w * u0.z; a0.w += w * u0.w;
        a1.x += w * u1.x; a1.y += w * u1.y; a1.z += w * u1.z; a1.w += w * u1.w;
    }
#pragma unroll
    for (int i = 3; i < 13; i++) {
        if (val[i]) {                   // warp-uniform branch
            float w = __expf(pd[i] - m);
            denom += w;
            const float4* vr = (const float4*)(sV + rows[i - 2] * DD);
            float4 y0 = vr[sub], y1 = vr[sub + 8];
            a0.x += w * y0.x; a0.y += w * y0.y; a0.z += w * y0.z; a0.w += w * y0.w;
            a1.x += w * y1.x; a1.y += w * y1.y; a1.z += w * y1.z; a1.w += w * y1.w;
        }
    }
    float inv = 1.0f / denom;
    a0.x *= inv; a0.y *= inv; a0.z *= inv; a0.w *= inv;
    a1.x *= inv; a1.y *= inv; a1.z *= inv; a1.w *= inv;
    ((float4*)(out + qoff))[sub]     = a0;
    ((float4*)(out + qoff))[sub + 8] = a1;
}

extern "C" void kernel_launch(void* const* d_in, const int* in_sizes, int n_in,
                              void* d_out, int out_size) {
    const float* q = (const float*)d_in[0];
    const float* k = (const float*)d_in[1];
    const float* v = (const float*)d_in[2];
    float* out = (float*)d_out;

    build5<<<NBH * CPB, 128>>>(k, v);
    build_high<<<NBH, 512>>>();
    attn<<<NBH * CPB, 256>>>(q, k, v, out);
}

// round 12
// speedup vs baseline: 1.0848x; 1.0341x over previous
#include <cuda_runtime.h>
#include <math.h>

#define BB 4
#define SS 4096
#define HH 8
#define DD 64
#define HD (HH*DD)
#define SCALE 0.125f
#define NBH (BB*HH)          // 32 (b,h) pairs
#define CH 32                // leaves per chunk
#define CPB (SS/CH)          // 128 chunks per bh
#define HI_NODES 254         // levels 5..11 per bh

// Global storage for tree levels 5..11 only (~2MB each, L2-resident).
__device__ float g_hiK[(size_t)NBH * HI_NODES * DD];
__device__ float g_hiV[(size_t)NBH * HI_NODES * DD];

__device__ __forceinline__ int hioff(int j) { return 256 - (256 >> j); }

// ---------- 8-lane-group softmax pool ----------
__device__ __forceinline__ void pool8(const float* __restrict__ kc0,
                                      const float* __restrict__ kc1,
                                      const float* __restrict__ vc0,
                                      const float* __restrict__ vc1,
                                      float* __restrict__ kout,
                                      float* __restrict__ vout,
                                      int sub, unsigned mask) {
    float4 a0 = ((const float4*)kc0)[sub], a1 = ((const float4*)kc0)[sub + 8];
    float4 b0 = ((const float4*)kc1)[sub], b1 = ((const float4*)kc1)[sub + 8];
    float4 p0, p1;
    p0.x = 0.5f * (a0.x + b0.x); p0.y = 0.5f * (a0.y + b0.y);
    p0.z = 0.5f * (a0.z + b0.z); p0.w = 0.5f * (a0.w + b0.w);
    p1.x = 0.5f * (a1.x + b1.x); p1.y = 0.5f * (a1.y + b1.y);
    p1.z = 0.5f * (a1.z + b1.z); p1.w = 0.5f * (a1.w + b1.w);
    float ds = p0.x*p0.x + p0.y*p0.y + p0.z*p0.z + p0.w*p0.w
             + p1.x*p1.x + p1.y*p1.y + p1.z*p1.z + p1.w*p1.w;
    float d0 = p0.x*a0.x + p0.y*a0.y + p0.z*a0.z + p0.w*a0.w
             + p1.x*a1.x + p1.y*a1.y + p1.z*a1.z + p1.w*a1.w;
    float d1 = p0.x*b0.x + p0.y*b0.y + p0.z*b0.z + p0.w*b0.w
             + p1.x*b1.x + p1.y*b1.y + p1.z*b1.z + p1.w*b1.w;
#pragma unroll
    for (int o = 4; o; o >>= 1) {
        ds += __shfl_xor_sync(mask, ds, o);
        d0 += __shfl_xor_sync(mask, d0, o);
        d1 += __shfl_xor_sync(mask, d1, o);
    }
    float ss = ds * SCALE, s0 = d0 * SCALE, s1 = d1 * SCALE;
    float m  = fmaxf(ss, fmaxf(s0, s1));
    float es = __expf(ss - m), e0 = __expf(s0 - m), e1 = __expf(s1 - m);
    float inv = 1.0f / (es + e0 + e1 + 1e-9f);
    float hes = 0.5f * es;
    float4 va0 = ((const float4*)vc0)[sub], va1 = ((const float4*)vc0)[sub + 8];
    float4 vb0 = ((const float4*)vc1)[sub], vb1 = ((const float4*)vc1)[sub + 8];
    float4 o0, o1;
    o0.x = (hes*(va0.x+vb0.x) + e0*va0.x + e1*vb0.x) * inv;
    o0.y = (hes*(va0.y+vb0.y) + e0*va0.y + e1*vb0.y) * inv;
    o0.z = (hes*(va0.z+vb0.z) + e0*va0.z + e1*vb0.z) * inv;
    o0.w = (hes*(va0.w+vb0.w) + e0*va0.w + e1*vb0.w) * inv;
    o1.x = (hes*(va1.x+vb1.x) + e0*va1.x + e1*vb1.x) * inv;
    o1.y = (hes*(va1.y+vb1.y) + e0*va1.y + e1*vb1.y) * inv;
    o1.z = (hes*(va1.z+vb1.z) + e0*va1.z + e1*vb1.z) * inv;
    o1.w = (hes*(va1.w+vb1.w) + e0*va1.w + e1*vb1.w) * inv;
    ((float4*)kout)[sub] = p0;  ((float4*)kout)[sub + 8] = p1;
    ((float4*)vout)[sub] = o0;  ((float4*)vout)[sub + 8] = o1;
}

// ---------- Pass 1: per 32-leaf chunk, emit level-5 node (unchanged) ----------
__global__ __launch_bounds__(128, 12) void build5(const float* __restrict__ k,
                                                  const float* __restrict__ v) {
    __shared__ float sK[30 * DD], sV[30 * DD];
    int blk = blockIdx.x;
    int cc  = blk & (CPB - 1);
    int bh  = blk >> 7;
    int b = bh >> 3, h = bh & 7;
    int tid = threadIdx.x, warp = tid >> 5, lane = tid & 31;
    int g = lane >> 3, sub = lane & 7;
    unsigned gmask = 0xFFu << (g * 8);
    int slot = warp * 4 + g;

    const float* leafK = k + ((size_t)(b * SS + cc * CH) * HH + h) * DD;
    const float* leafV = v + ((size_t)(b * SS + cc * CH) * HH + h) * DD;

    pool8(leafK + (size_t)(2 * slot) * HD, leafK + (size_t)(2 * slot + 1) * HD,
          leafV + (size_t)(2 * slot) * HD, leafV + (size_t)(2 * slot + 1) * HD,
          sK + slot * DD, sV + slot * DD, sub, gmask);
    __syncthreads();
    if (slot < 8)
        pool8(sK + (2 * slot) * DD, sK + (2 * slot + 1) * DD,
              sV + (2 * slot) * DD, sV + (2 * slot + 1) * DD,
              sK + (16 + slot) * DD, sV + (16 + slot) * DD, sub, gmask);
    __syncthreads();
    if (warp == 0) {
        pool8(sK + (16 + 2 * g) * DD, sK + (16 + 2 * g + 1) * DD,
              sV + (16 + 2 * g) * DD, sV + (16 + 2 * g + 1) * DD,
              sK + (24 + g) * DD, sV + (24 + g) * DD, sub, gmask);
        __syncwarp();
        if (g < 2)
            pool8(sK + (24 + 2 * g) * DD, sK + (24 + 2 * g + 1) * DD,
                  sV + (24 + 2 * g) * DD, sV + (24 + 2 * g + 1) * DD,
                  sK + (28 + g) * DD, sV + (28 + g) * DD, sub, gmask);
        __syncwarp();
        if (g == 0) {
            size_t o = ((size_t)bh * HI_NODES + cc) * DD;
            pool8(sK + 28 * DD, sK + 29 * DD, sV + 28 * DD, sV + 29 * DD,
                  g_hiK + o, g_hiV + o, sub, 0xFFu);
        }
    }
}

// ---------- Pass 2: per bh, levels 6..11 (pool8, one round per level) ----------
__global__ __launch_bounds__(512) void build_high() {
    int bh = blockIdx.x;
    int tid = threadIdx.x, warp = tid >> 5, lane = tid & 31;
    int g = lane >> 3, sub = lane & 7;
    unsigned gmask = 0xFFu << (g * 8);
    int gid = warp * 4 + g;          // 0..63
    size_t base = (size_t)bh * HI_NODES * DD;

    int off_prev = 0, off = 128, cnt = 64;
#pragma unroll
    for (int l = 6; l <= 11; l++) {
        if (gid < cnt)
            pool8(g_hiK + base + (size_t)(off_prev + 2 * gid) * DD,
                  g_hiK + base + (size_t)(off_prev + 2 * gid + 1) * DD,
                  g_hiV + base + (size_t)(off_prev + 2 * gid) * DD,
                  g_hiV + base + (size_t)(off_prev + 2 * gid + 1) * DD,
                  g_hiK + base + (size_t)(off + gid) * DD,
                  g_hiV + base + (size_t)(off + gid) * DD, sub, gmask);
        __syncthreads();
        off_prev = off;
        off += cnt;
        cnt >>= 1;
    }
}

// ---------- Pass 3: fused attention ----------
// Smem rows: L1 0..15, L2 16..23, L3 24..27, L4 28..29, HI 30..36 (37 rows).
// Dead rows: L1 {15}, L2 {7}, L3 {3}, L4 {1}.
#define R_L2 16
#define R_L3 24
#define R_L4 28
#define R_HI 30

__device__ __forceinline__ float4 lds4_pred(const float4* p, bool pr) {
    float4 r = {0.f, 0.f, 0.f, 0.f};
    if (pr) r = *p;
    return r;
}
__device__ __forceinline__ float4 ldcs4(const float* p) {
    return __ldcs((const float4*)p);
}

__global__ __launch_bounds__(256, 5) void attn(const float* __restrict__ q,
                                               const float* __restrict__ k,
                                               const float* __restrict__ v,
                                               float* __restrict__ out) {
    __shared__ float sK[37 * DD], sV[37 * DD];
    int blk = blockIdx.x;
    int cc  = blk & (CPB - 1);
    int bh  = blk >> 7;
    int b = bh >> 3, h = bh & 7;
    int tid = threadIdx.x, warp = tid >> 5, lane = tid & 31;
    int g = lane >> 3, sub = lane & 7;
    unsigned gmask = 0xFFu << (g * 8);
    int qid = tid >> 3;

    const float* leafK = k + ((size_t)(b * SS + cc * CH) * HH + h) * DD;
    const float* leafV = v + ((size_t)(b * SS + cc * CH) * HH + h) * DD;

    // q: streaming load (single-use; don't pollute L2 holding k/v)
    // float4 index sub -> float offset 4*sub.
    size_t qoff = ((size_t)(b * SS + cc * CH + qid) * HH + h) * DD;
    float4 q0 = ldcs4(q + qoff + 4 * sub);
    float4 q1 = ldcs4(q + qoff + 4 * (sub + 8));

    // slot metadata (pure ALU)
    int rows[11];
    bool val[13];
    val[0] = true;
    val[1] = (qid & 1);
    const int tbase[4] = {0, R_L2, R_L3, R_L4};
#pragma unroll
    for (int l = 1; l <= 4; l++) {
        int n = qid >> l;
        rows[l - 1] = tbase[l - 1] + ((n > 0) ? n - 1 : 0);
        val[1 + l]  = (n & 1);
    }
#pragma unroll
    for (int j = 0; j < 7; j++) {
        rows[4 + j] = R_HI + j;
        val[6 + j]  = ((cc >> j) & 1);
    }
    const float* selfK = leafK + (size_t)qid * HD;
    const float* selfV = leafV + (size_t)qid * HD;
    int sib = (qid > 0) ? qid - 1 : 0;
    const float* sibK = leafK + (size_t)sib * HD;
    const float* sibV = leafV + (size_t)sib * HD;

    // ---- phase A: L1 pools (warps 0-3) + hi staging (warps 4-7) ----
    if (warp < 4) {
        int slot = warp * 4 + g;
        if (slot != 15)                 // dead L1 row
            pool8(leafK + (size_t)(2 * slot) * HD, leafK + (size_t)(2 * slot + 1) * HD,
                  leafV + (size_t)(2 * slot) * HD, leafV + (size_t)(2 * slot + 1) * HD,
                  sK + slot * DD, sV + slot * DD, sub, gmask);
    } else {
        int j = (warp - 4) * 4 + g;
        if (j < 7) {
            int n = cc >> j;
            int node = (n > 0) ? n - 1 : 0;
            const float* hk = g_hiK + ((size_t)bh * HI_NODES + hioff(j) + node) * DD;
            const float* hv = g_hiV + ((size_t)bh * HI_NODES + hioff(j) + node) * DD;
            ((float4*)(sK + (R_HI + j) * DD))[sub]     = ((const float4*)hk)[sub];
            ((float4*)(sK + (R_HI + j) * DD))[sub + 8] = ((const float4*)hk)[sub + 8];
            ((float4*)(sV + (R_HI + j) * DD))[sub]     = ((const float4*)hv)[sub];
            ((float4*)(sV + (R_HI + j) * DD))[sub + 8] = ((const float4*)hv)[sub + 8];
        }
    }
    __syncthreads();                    // barrier 1

    float pd[13];
    // dots independent of the L2-L4 tree: slots 0,1 (leaf, L1-hot), 2 (L1 row),
    // 6..12 (hi rows). Computed by warps 2-7 while warps 0-1 build the tree.
    auto mid_dots = [&]() {
        float4 x0 = ((const float4*)selfK)[sub], x1 = ((const float4*)selfK)[sub + 8];
        pd[0] = q0.x*x0.x + q0.y*x0.y + q0.z*x0.z + q0.w*x0.w
              + q1.x*x1.x + q1.y*x1.y + q1.z*x1.z + q1.w*x1.w;
        float4 y0 = lds4_pred((const float4*)sibK + sub, val[1]);
        float4 y1 = lds4_pred((const float4*)sibK + sub + 8, val[1]);
        pd[1] = q0.x*y0.x + q0.y*y0.y + q0.z*y0.z + q0.w*y0.w
              + q1.x*y1.x + q1.y*y1.y + q1.z*y1.z + q1.w*y1.w;
        const float4* kr = (const float4*)(sK + rows[0] * DD);
        float4 z0 = lds4_pred(kr + sub, val[2]);
        float4 z1 = lds4_pred(kr + sub + 8, val[2]);
        pd[2] = q0.x*z0.x + q0.y*z0.y + q0.z*z0.z + q0.w*z0.w
              + q1.x*z1.x + q1.y*z1.y + q1.z*z1.z + q1.w*z1.w;
#pragma unroll
        for (int i = 6; i < 13; i++) {
            pd[i] = 0.0f;
            if (val[i]) {               // block-uniform branch
                const float4* hr = (const float4*)(sK + rows[i - 2] * DD);
                float4 u0 = hr[sub], u1 = hr[sub + 8];
                pd[i] = q0.x*u0.x + q0.y*u0.y + q0.z*u0.z + q0.w*u0.w
                      + q1.x*u1.x + q1.y*u1.y + q1.z*u1.z + q1.w*u1.w;
            }
        }
    };

    if (warp == 0) {
        // chain A: L2 rows 0-3 -> L3 rows 0,1 -> L4 row 0
        pool8(sK + (2 * g) * DD, sK + (2 * g + 1) * DD,
              sV + (2 * g) * DD, sV + (2 * g + 1) * DD,
              sK + (R_L2 + g) * DD, sV + (R_L2 + g) * DD, sub, gmask);
        __syncwarp();
        if (g < 2)
            pool8(sK + (R_L2 + 2 * g) * DD, sK + (R_L2 + 2 * g + 1) * DD,
                  sV + (R_L2 + 2 * g) * DD, sV + (R_L2 + 2 * g + 1) * DD,
                  sK + (R_L3 + g) * DD, sV + (R_L3 + g) * DD, sub, gmask);
        __syncwarp();
        if (g == 0)
            pool8(sK + R_L3 * DD, sK + (R_L3 + 1) * DD,
                  sV + R_L3 * DD, sV + (R_L3 + 1) * DD,
                  sK + R_L4 * DD, sV + R_L4 * DD, sub, gmask);
    } else if (warp == 1) {
        // chain B: L2 rows 4-6 -> L3 row 2   (L2 row 7, L3 row 3 dead)
        if (g < 3)
            pool8(sK + (2 * (4 + g)) * DD, sK + (2 * (4 + g) + 1) * DD,
                  sV + (2 * (4 + g)) * DD, sV + (2 * (4 + g) + 1) * DD,
                  sK + (R_L2 + 4 + g) * DD, sV + (R_L2 + 4 + g) * DD, sub, gmask);
        __syncwarp();
        if (g == 0)
            pool8(sK + (R_L2 + 4) * DD, sK + (R_L2 + 5) * DD,
                  sV + (R_L2 + 4) * DD, sV + (R_L2 + 5) * DD,
                  sK + (R_L3 + 2) * DD, sV + (R_L3 + 2) * DD, sub, gmask);
    } else {
        mid_dots();
    }
    __syncthreads();                    // barrier 2
    if (warp < 2) mid_dots();

    // hoist self/sib V loads (L1-hot) ahead of remaining dots + butterfly
    float4 sv0 = ((const float4*)selfV)[sub], sv1 = ((const float4*)selfV)[sub + 8];
    float4 bv0 = lds4_pred((const float4*)sibV + sub, val[1]);
    float4 bv1 = lds4_pred((const float4*)sibV + sub + 8, val[1]);

    // remaining dots: slots 3..5 (need the tree), warp-uniform guards
#pragma unroll
    for (int i = 3; i < 6; i++) {
        pd[i] = 0.0f;
        if (val[i]) {
            const float4* kr = (const float4*)(sK + rows[i - 2] * DD);
            float4 x0 = kr[sub], x1 = kr[sub + 8];
            pd[i] = q0.x*x0.x + q0.y*x0.y + q0.z*x0.z + q0.w*x0.w
                  + q1.x*x1.x + q1.y*x1.y + q1.z*x1.z + q1.w*x1.w;
        }
    }
    // butterfly: always for slots 0..2, guarded for 3..12 (warp-uniform)
#pragma unroll
    for (int i = 0; i < 3; i++) {
#pragma unroll
        for (int o = 4; o; o >>= 1)
            pd[i] += __shfl_xor_sync(0xffffffffu, pd[i], o);
    }
#pragma unroll
    for (int i = 3; i < 13; i++) {
        if (val[i]) {
#pragma unroll
            for (int o = 4; o; o >>= 1)
                pd[i] += __shfl_xor_sync(0xffffffffu, pd[i], o);
        }
    }
    float m = -1e30f;
#pragma unroll
    for (int i = 0; i < 13; i++) {
        pd[i] = val[i] ? pd[i] * SCALE : -1e30f;
        m = fmaxf(m, pd[i]);
    }

    // fused exp + V accumulation
    float denom;
    float4 a0, a1;
    {
        float w = __expf(pd[0] - m);
        denom = w;
        a0.x = w * sv0.x; a0.y = w * sv0.y; a0.z = w * sv0.z; a0.w = w * sv0.w;
        a1.x = w * sv1.x; a1.y = w * sv1.y; a1.z = w * sv1.z; a1.w = w * sv1.w;
        w = val[1] ? __expf(pd[1] - m) : 0.0f;
        denom += w;
        a0.x += w * bv0.x; a0.y += w * bv0.y; a0.z += w * bv0.z; a0.w += w * bv0.w;
        a1.x += w * bv1.x; a1.y += w * bv1.y; a1.z += w * bv1.z; a1.w += w * bv1.w;
        w = val[2] ? __expf(pd[2] - m) : 0.0f;
        denom += w;
        const float4* vr = (const float4*)(sV + rows[0] * DD);
        float4 u0 = lds4_pred(vr + sub, val[2]);
        float4 u1 = lds4_pred(vr + sub + 8, val[2]);
        a0.x += w * u0.x; a0.y += w * u0.y; a0.z += w * u0.z; a0.w += w * u0.w;
        a1.x += w * u1.x; a1.y += w * u1.y; a1.z += w * u1.z; a1.w += w * u1.w;
    }
#pragma unroll
    for (int i = 3; i < 13; i++) {
        if (val[i]) {                   // warp-uniform branch
            float w = __expf(pd[i] - m);
            denom += w;
            const float4* vr = (const float4*)(sV + rows[i - 2] * DD);
            float4 y0 = vr[sub], y1 = vr[sub + 8];
            a0.x += w * y0.x; a0.y += w * y0.y; a0.z += w * y0.z; a0.w += w * y0.w;
            a1.x += w * y1.x; a1.y += w * y1.y; a1.z += w * y1.z; a1.w += w * y1.w;
        }
    }
    float inv = 1.0f / denom;
    a0.x *= inv; a0.y *= inv; a0.z *= inv; a0.w *= inv;
    a1.x *= inv; a1.y *= inv; a1.z *= inv; a1.w *= inv;
    // streaming stores (single-use; keep k/v in L2)
    __stcs((float4*)(out + qoff) + sub, a0);
    __stcs((float4*)(out + qoff) + sub + 8, a1);
}

extern "C" void kernel_launch(void* const* d_in, const int* in_sizes, int n_in,
                              void* d_out, int out_size) {
    const float* q = (const float*)d_in[0];
    const float* k = (const float*)d_in[1];
    const float* v = (const float*)d_in[2];
    float* out = (float*)d_out;

    build5<<<NBH * CPB, 128>>>(k, v);
    build_high<<<NBH, 512>>>();
    attn<<<NBH * CPB, 256>>>(q, k, v, out);
}